// round 1
// baseline (speedup 1.0000x reference)
#include <cuda_runtime.h>

#define BB 4
#define NH 8
#define DD 16
#define LC 1024
#define WCC 32
#define LF 4096
#define WFF 64
#define TOPK 8
#define KVPAD 20   // 80B row stride: conflict-free for float4 at 32-elt lane stride

// ---------------- scratch (device globals; no allocation) ----------------
__device__ float g_qc[BB*NH*LC*DD];
__device__ float g_kc[BB*NH*LC*DD];
__device__ float g_vc[BB*NH*LC*DD];
__device__ float g_qf[BB*NH*LF*DD];
__device__ float g_kf[BB*NH*LF*DD];
__device__ float g_vf[BB*NH*LF*DD];
__device__ float g_msg0[BB*NH*LC*DD];
__device__ int   g_topk[BB*NH*LC*TOPK];

// ---------------- transpose [B,C,P] -> [B,H,P,16] (optionally scale) -----
__global__ void transpose_kernel(const float* __restrict__ in,
                                 float* __restrict__ out, int P, float scale) {
    int t = blockIdx.x * blockDim.x + threadIdx.x;
    int total = BB * NH * P;
    if (t >= total) return;
    int p  = t % P;
    int bh = t / P;
    const float* src = in + ((size_t)bh * DD) * P + p;
    float v[DD];
#pragma unroll
    for (int d = 0; d < DD; d++) v[d] = src[(size_t)d * P] * scale;
    float4* o = reinterpret_cast<float4*>(out + ((size_t)bh * P + p) * DD);
#pragma unroll
    for (int j = 0; j < 4; j++)
        o[j] = make_float4(v[4*j], v[4*j+1], v[4*j+2], v[4*j+3]);
}

// composite order: descending value, ties -> lower index first (matches lax.top_k)
__device__ __forceinline__ bool keygt(float av, int ai, float bv, int bi) {
    return (av > bv) || (av == bv && ai < bi);
}

__device__ __forceinline__ float dot16(float4 a0, float4 a1, float4 a2, float4 a3,
                                       float4 b0, float4 b1, float4 b2, float4 b3) {
    float s = a0.x*b0.x + a0.y*b0.y + a0.z*b0.z + a0.w*b0.w;
    s += a1.x*b1.x + a1.y*b1.y + a1.z*b1.z + a1.w*b1.w;
    s += a2.x*b2.x + a2.y*b2.y + a2.z*b2.z + a2.w*b2.w;
    s += a3.x*b3.x + a3.y*b3.y + a3.z*b3.z + a3.w*b3.w;
    return s;
}

// exact top-8 merge for one row; returns row max. rowS holds raw scores.
__device__ __forceinline__ float topk_merge(float v1, int i1, float v2, int i2,
                                            const float* __restrict__ rowS,
                                            int lane, int* __restrict__ gout) {
    float bv = v1; int bi = i1;
    float lcv = 0.f; int lci = 0; int cc = 0;
    float rowmax = -1e30f;
    int myidx = 0;
#pragma unroll 1
    for (int pick = 0; pick < TOPK; pick++) {
        float wv = bv; int wi = bi;
#pragma unroll
        for (int off = 16; off; off >>= 1) {
            float ov = __shfl_xor_sync(0xffffffffu, wv, off);
            int   oi = __shfl_xor_sync(0xffffffffu, wi, off);
            if (keygt(ov, oi, wv, wi)) { wv = ov; wi = oi; }
        }
        if (pick == 0) rowmax = wv;
        if (lane == pick) myidx = wi;
        if (bi == wi) {              // this lane's candidate was consumed
            cc++; lcv = wv; lci = wi;
            if (cc == 1) { bv = v2; bi = i2; }
            else {                   // rescan own strided values below threshold
                bv = -1e30f; bi = 0x7fffffff;
#pragma unroll 1
                for (int i = 0; i < 32; i++) {
                    int s = i * 32 + lane;
                    float e = rowS[s];
                    if (keygt(lcv, lci, e, s) && keygt(e, s, bv, bi)) { bv = e; bi = s; }
                }
            }
        }
    }
    if (lane < TOPK) gout[lane] = myidx;
    return rowmax;
}

// ---------------- coarse level ----------------
// grid (32 l-tiles, 32 bh), 512 threads. smem: K/V buf + raw-score/exp buffer + Q tile
#define SMEM_FLOATS (LC*KVPAD + 32*LC + 32*DD)

__global__ void __launch_bounds__(512, 1) coarse_kernel() {
    extern __shared__ float sm[];
    float* sKV = sm;                  // 1024 x 20
    float* sS  = sm + LC * KVPAD;     // 32 x 1024
    float* sQ  = sS + 32 * LC;        // 32 x 16
    int tid = threadIdx.x;
    int w = tid >> 5, lane = tid & 31;
    int bh = blockIdx.y;
    int lbase = blockIdx.x * 32;
    const float* Qg = g_qc + ((size_t)bh * LC + lbase) * DD;
    const float* Kg = g_kc + (size_t)bh * LC * DD;
    const float* Vg = g_vc + (size_t)bh * LC * DD;

    sQ[tid] = Qg[tid];
    {
        const float4* K4 = reinterpret_cast<const float4*>(Kg);
#pragma unroll
        for (int i = tid; i < LC * DD / 4; i += 512) {
            int s = i >> 2, j = i & 3;
            *reinterpret_cast<float4*>(&sKV[s * KVPAD + j * 4]) = K4[i];
        }
    }
    __syncthreads();

    int r0 = 2 * w, r1 = 2 * w + 1;
    float4 qa[4], qb[4];
#pragma unroll
    for (int j = 0; j < 4; j++) {
        qa[j] = *reinterpret_cast<const float4*>(&sQ[r0 * DD + 4 * j]);
        qb[j] = *reinterpret_cast<const float4*>(&sQ[r1 * DD + 4 * j]);
    }

    // ---- raw scores + per-lane top-2 (exact fp32 for top-k) ----
    float a1v = -1e30f, a2v = -1e30f; int a1i = -1, a2i = -1;
    float b1v = -1e30f, b2v = -1e30f; int b1i = -1, b2i = -1;
#pragma unroll 4
    for (int i = 0; i < 32; i++) {
        int s = i * 32 + lane;
        const float* kp = &sKV[s * KVPAD];
        float4 k0 = *(const float4*)(kp);
        float4 k1 = *(const float4*)(kp + 4);
        float4 k2 = *(const float4*)(kp + 8);
        float4 k3 = *(const float4*)(kp + 12);
        float s0 = dot16(qa[0], qa[1], qa[2], qa[3], k0, k1, k2, k3);
        float s1 = dot16(qb[0], qb[1], qb[2], qb[3], k0, k1, k2, k3);
        sS[r0 * LC + s] = s0;
        sS[r1 * LC + s] = s1;
        if (keygt(s0, s, a1v, a1i)) { a2v = a1v; a2i = a1i; a1v = s0; a1i = s; }
        else if (keygt(s0, s, a2v, a2i)) { a2v = s0; a2i = s; }
        if (keygt(s1, s, b1v, b1i)) { b2v = b1v; b2i = b1i; b1v = s1; b1i = s; }
        else if (keygt(s1, s, b2v, b2i)) { b2v = s1; b2i = s; }
    }

    // ---- exact top-8 per row (on raw scores; softmax is monotone) ----
    float max0 = topk_merge(a1v, a1i, a2v, a2i, sS + r0 * LC, lane,
                            g_topk + ((size_t)bh * LC + lbase + r0) * TOPK);
    float max1 = topk_merge(b1v, b1i, b2v, b2i, sS + r1 * LC, lane,
                            g_topk + ((size_t)bh * LC + lbase + r1) * TOPK);

    // ---- exp + row sums (overwrite score buffer with e) ----
    float sum0 = 0.f, sum1 = 0.f;
#pragma unroll 4
    for (int i = 0; i < 32; i++) {
        int s = i * 32 + lane;
        float e0 = __expf(sS[r0 * LC + s] - max0);
        float e1 = __expf(sS[r1 * LC + s] - max1);
        sS[r0 * LC + s] = e0;
        sS[r1 * LC + s] = e1;
        sum0 += e0; sum1 += e1;
    }
#pragma unroll
    for (int off = 16; off; off >>= 1) {
        sum0 += __shfl_xor_sync(0xffffffffu, sum0, off);
        sum1 += __shfl_xor_sync(0xffffffffu, sum1, off);
    }
    float rs0 = 1.f / sum0, rs1 = 1.f / sum1;

    __syncthreads();   // done with K
    {
        const float4* V4 = reinterpret_cast<const float4*>(Vg);
#pragma unroll
        for (int i = tid; i < LC * DD / 4; i += 512) {
            int s = i >> 2, j = i & 3;
            *reinterpret_cast<float4*>(&sKV[s * KVPAD + j * 4]) = V4[i];
        }
    }
    __syncthreads();

    // ---- msg0 = softmax(S) @ V ----
    float4 ac0[4], ac1[4];
#pragma unroll
    for (int j = 0; j < 4; j++) {
        ac0[j] = make_float4(0.f, 0.f, 0.f, 0.f);
        ac1[j] = make_float4(0.f, 0.f, 0.f, 0.f);
    }
#pragma unroll 4
    for (int i = 0; i < 32; i++) {
        int s = i * 32 + lane;
        float e0 = sS[r0 * LC + s];
        float e1 = sS[r1 * LC + s];
        const float* vp = &sKV[s * KVPAD];
        float4 v0 = *(const float4*)(vp);
        float4 v1 = *(const float4*)(vp + 4);
        float4 v2 = *(const float4*)(vp + 8);
        float4 v3 = *(const float4*)(vp + 12);
        ac0[0].x += e0*v0.x; ac0[0].y += e0*v0.y; ac0[0].z += e0*v0.z; ac0[0].w += e0*v0.w;
        ac0[1].x += e0*v1.x; ac0[1].y += e0*v1.y; ac0[1].z += e0*v1.z; ac0[1].w += e0*v1.w;
        ac0[2].x += e0*v2.x; ac0[2].y += e0*v2.y; ac0[2].z += e0*v2.z; ac0[2].w += e0*v2.w;
        ac0[3].x += e0*v3.x; ac0[3].y += e0*v3.y; ac0[3].z += e0*v3.z; ac0[3].w += e0*v3.w;
        ac1[0].x += e1*v0.x; ac1[0].y += e1*v0.y; ac1[0].z += e1*v0.z; ac1[0].w += e1*v0.w;
        ac1[1].x += e1*v1.x; ac1[1].y += e1*v1.y; ac1[1].z += e1*v1.z; ac1[1].w += e1*v1.w;
        ac1[2].x += e1*v2.x; ac1[2].y += e1*v2.y; ac1[2].z += e1*v2.z; ac1[2].w += e1*v2.w;
        ac1[3].x += e1*v3.x; ac1[3].y += e1*v3.y; ac1[3].z += e1*v3.z; ac1[3].w += e1*v3.w;
    }
#pragma unroll
    for (int off = 16; off; off >>= 1) {
#pragma unroll
        for (int j = 0; j < 4; j++) {
            ac0[j].x += __shfl_xor_sync(0xffffffffu, ac0[j].x, off);
            ac0[j].y += __shfl_xor_sync(0xffffffffu, ac0[j].y, off);
            ac0[j].z += __shfl_xor_sync(0xffffffffu, ac0[j].z, off);
            ac0[j].w += __shfl_xor_sync(0xffffffffu, ac0[j].w, off);
            ac1[j].x += __shfl_xor_sync(0xffffffffu, ac1[j].x, off);
            ac1[j].y += __shfl_xor_sync(0xffffffffu, ac1[j].y, off);
            ac1[j].z += __shfl_xor_sync(0xffffffffu, ac1[j].z, off);
            ac1[j].w += __shfl_xor_sync(0xffffffffu, ac1[j].w, off);
        }
    }
    if (lane == 0) {
        float4* o = (float4*)(g_msg0 + ((size_t)bh * LC + lbase + r0) * DD);
#pragma unroll
        for (int j = 0; j < 4; j++)
            o[j] = make_float4(ac0[j].x*rs0, ac0[j].y*rs0, ac0[j].z*rs0, ac0[j].w*rs0);
    }
    if (lane == 1) {
        float4* o = (float4*)(g_msg0 + ((size_t)bh * LC + lbase + r1) * DD);
#pragma unroll
        for (int j = 0; j < 4; j++)
            o[j] = make_float4(ac1[j].x*rs1, ac1[j].y*rs1, ac1[j].z*rs1, ac1[j].w*rs1);
    }
}

// ---------------- fine level + combine ----------------
// warp per (b,h,l): 32 lanes = 32 candidates (8 coarse picks x 2x2 children)
__global__ void __launch_bounds__(256) fine_kernel(const float* __restrict__ wptr,
                                                   float* __restrict__ out) {
    __shared__ float sQ[8][4][16];
    __shared__ float sP[8][32][4];
    __shared__ float sV[8][32][KVPAD];
    int tid = threadIdx.x, w = tid >> 5, lane = tid & 31;
    int gw = blockIdx.x * 8 + w;
    int bh = gw >> 10;
    int l  = gw & 1023;
    int b = bh >> 3, h = bh & 7;
    int lh = l >> 5, lw = l & 31;

    float w0 = wptr[0], w1 = wptr[1];
    float mw = fmaxf(w0, w1);
    float ew0 = __expf(w0 - mw), ew1 = __expf(w1 - mw);
    float rw = 1.f / (ew0 + ew1);
    float wa = ew0 * rw, wb = ew1 * rw;

    int cr = lane >> 2, off2 = lane & 3, ox = off2 >> 1, oy = off2 & 1;
    int cidx = g_topk[((size_t)bh * LC + l) * TOPK + cr];
    int py = cidx >> 5, px = cidx & (WCC - 1);
    int pos = (2 * py + ox) * WFF + 2 * px + oy;

    const float4* kp = (const float4*)(g_kf + ((size_t)bh * LF + pos) * DD);
    float4 k0 = kp[0], k1 = kp[1], k2 = kp[2], k3 = kp[3];
    const float4* vp = (const float4*)(g_vf + ((size_t)bh * LF + pos) * DD);
    float4 v0 = vp[0], v1 = vp[1], v2 = vp[2], v3 = vp[3];

    if (lane < 16) {
        int qq = lane >> 2, j = lane & 3;
        int qpos = (2 * lh + (qq >> 1)) * WFF + 2 * lw + (qq & 1);
        float4 qv = ((const float4*)(g_qf + ((size_t)bh * LF + qpos) * DD))[j];
        *reinterpret_cast<float4*>(&sQ[w][qq][4 * j]) = qv;
    }
    __syncwarp();

    float p[4];
#pragma unroll
    for (int qq = 0; qq < 4; qq++) {
        const float4* q4 = (const float4*)sQ[w][qq];
        float sc = dot16(q4[0], q4[1], q4[2], q4[3], k0, k1, k2, k3);
        float m = sc;
#pragma unroll
        for (int o = 16; o; o >>= 1) m = fmaxf(m, __shfl_xor_sync(0xffffffffu, m, o));
        float e = __expf(sc - m);
        float s = e;
#pragma unroll
        for (int o = 16; o; o >>= 1) s += __shfl_xor_sync(0xffffffffu, s, o);
        p[qq] = e / s;
    }
    *reinterpret_cast<float4*>(&sP[w][lane][0]) = make_float4(p[0], p[1], p[2], p[3]);
    float* vr = &sV[w][lane][0];
    *(float4*)(vr) = v0; *(float4*)(vr + 4) = v1;
    *(float4*)(vr + 8) = v2; *(float4*)(vr + 12) = v3;
    __syncwarp();

    int qq = lane >> 3, dp = lane & 7, d0 = dp * 2;
    float accx = 0.f, accy = 0.f;
#pragma unroll
    for (int c = 0; c < 32; c++) {
        float pc = sP[w][c][qq];
        float2 vv = *reinterpret_cast<const float2*>(&sV[w][c][d0]);
        accx += pc * vv.x;
        accy += pc * vv.y;
    }
    const float* m0p = g_msg0 + ((size_t)bh * LC + l) * DD + d0;
    float o0 = wa * m0p[0] + wb * accx;
    float o1 = wa * m0p[1] + wb * accy;
    int opos = (2 * lh + (qq >> 1)) * WFF + 2 * lw + (qq & 1);
    float* op = out + (((size_t)b * LF + opos) * NH + h) * DD + d0;
    *reinterpret_cast<float2*>(op) = make_float2(o0, o1);
}

// ---------------- launcher ----------------
extern "C" void kernel_launch(void* const* d_in, const int* in_sizes, int n_in,
                              void* d_out, int out_size) {
    (void)in_sizes; (void)n_in; (void)out_size;
    const float* qf = (const float*)d_in[0];
    const float* qc = (const float*)d_in[1];
    const float* kf = (const float*)d_in[2];
    const float* kc = (const float*)d_in[3];
    const float* vf = (const float*)d_in[4];
    const float* vc = (const float*)d_in[5];
    const float* wt = (const float*)d_in[6];
    float* out = (float*)d_out;

    void *p_qc, *p_kc, *p_vc, *p_qf, *p_kf, *p_vf;
    cudaGetSymbolAddress(&p_qc, g_qc);
    cudaGetSymbolAddress(&p_kc, g_kc);
    cudaGetSymbolAddress(&p_vc, g_vc);
    cudaGetSymbolAddress(&p_qf, g_qf);
    cudaGetSymbolAddress(&p_kf, g_kf);
    cudaGetSymbolAddress(&p_vf, g_vf);

    const float temp = 0.25f;  // 1/sqrt(16), folded into Q
    int tc = BB * NH * LC, tf = BB * NH * LF;
    transpose_kernel<<<(tc + 255) / 256, 256>>>(qc, (float*)p_qc, LC, temp);
    transpose_kernel<<<(tc + 255) / 256, 256>>>(kc, (float*)p_kc, LC, 1.f);
    transpose_kernel<<<(tc + 255) / 256, 256>>>(vc, (float*)p_vc, LC, 1.f);
    transpose_kernel<<<(tf + 255) / 256, 256>>>(qf, (float*)p_qf, LF, temp);
    transpose_kernel<<<(tf + 255) / 256, 256>>>(kf, (float*)p_kf, LF, 1.f);
    transpose_kernel<<<(tf + 255) / 256, 256>>>(vf, (float*)p_vf, LF, 1.f);

    size_t smem = SMEM_FLOATS * sizeof(float);
    cudaFuncSetAttribute(coarse_kernel, cudaFuncAttributeMaxDynamicSharedMemorySize,
                         (int)smem);
    coarse_kernel<<<dim3(32, 32), 512, smem>>>();

    fine_kernel<<<4096, 256>>>(wt, out);
}

// round 2
// speedup vs baseline: 1.2121x; 1.2121x over previous
#include <cuda_runtime.h>

#define BB 4
#define NH 8
#define DD 16
#define LC 1024
#define WCC 32
#define LF 4096
#define WFF 64
#define TOPK 8
#define KVPAD 20   // 80B row stride: conflict-free for float4 at 32-elt lane stride

// ---------------- scratch (device globals; no allocation) ----------------
__device__ float g_qc[BB*NH*LC*DD];
__device__ float g_kc[BB*NH*LC*DD];
__device__ float g_vc[BB*NH*LC*DD];
__device__ float g_qf[BB*NH*LF*DD];
__device__ float g_kf[BB*NH*LF*DD];
__device__ float g_vf[BB*NH*LF*DD];
__device__ float g_msg0[BB*NH*LC*DD];
__device__ int   g_topk[BB*NH*LC*TOPK];

// ---------------- tiled transpose: [BH,16,P] -> [BH,P,16], q scaled ------
// grid (P/256, 32, 3), block 256. z selects q/k/v.
__global__ void __launch_bounds__(256) transpose3_kernel(
        const float* __restrict__ q, const float* __restrict__ k,
        const float* __restrict__ v, float* __restrict__ oq,
        float* __restrict__ ok, float* __restrict__ ov, int P, float qscale) {
    __shared__ float tile[16 * 260];
    int z = blockIdx.z;
    const float* in = (z == 0) ? q : (z == 1) ? k : v;
    float* out = (z == 0) ? oq : (z == 1) ? ok : ov;
    float scale = (z == 0) ? qscale : 1.f;
    int bh = blockIdx.y;
    int p0 = blockIdx.x * 256;
    int t = threadIdx.x;
    const float4* src = reinterpret_cast<const float4*>(in + (size_t)bh * DD * P + p0);
    int Pq = P >> 2;
#pragma unroll
    for (int j = 0; j < 4; j++) {
        int f = t + 256 * j;          // float4 index in [0,1024)
        int d = f >> 6, c4 = f & 63;
        float4 val = src[(size_t)d * Pq + c4];
        val.x *= scale; val.y *= scale; val.z *= scale; val.w *= scale;
        *reinterpret_cast<float4*>(&tile[d * 260 + c4 * 4]) = val;
    }
    __syncthreads();
    float o[16];
#pragma unroll
    for (int d = 0; d < 16; d++) o[d] = tile[d * 260 + t];
    float4* dst = reinterpret_cast<float4*>(out + ((size_t)bh * P + p0 + t) * DD);
    dst[0] = make_float4(o[0], o[1], o[2], o[3]);
    dst[1] = make_float4(o[4], o[5], o[6], o[7]);
    dst[2] = make_float4(o[8], o[9], o[10], o[11]);
    dst[3] = make_float4(o[12], o[13], o[14], o[15]);
}

// ---------------- packed sort key: value desc, ties -> lower index -------
__device__ __forceinline__ unsigned long long packkey(float f, int s) {
    unsigned u = __float_as_uint(f);
    u ^= ((unsigned)((int)u >> 31)) | 0x80000000u;
    return ((unsigned long long)u << 32) | (unsigned)(2047 - s);
}
__device__ __forceinline__ float unpackval(unsigned long long k) {
    unsigned su = (unsigned)(k >> 32);
    unsigned u = (su & 0x80000000u) ? (su ^ 0x80000000u) : ~su;
    return __uint_as_float(u);
}
__device__ __forceinline__ int unpackidx(unsigned long long k) {
    return 2047 - (int)(k & 0xffffffffu);
}

__device__ __forceinline__ float dot16(float4 a0, float4 a1, float4 a2, float4 a3,
                                       float4 b0, float4 b1, float4 b2, float4 b3) {
    float s = a0.x*b0.x + a0.y*b0.y + a0.z*b0.z + a0.w*b0.w;
    s += a1.x*b1.x + a1.y*b1.y + a1.z*b1.z + a1.w*b1.w;
    s += a2.x*b2.x + a2.y*b2.y + a2.z*b2.z + a2.w*b2.w;
    s += a3.x*b3.x + a3.y*b3.y + a3.z*b3.z + a3.w*b3.w;
    return s;
}

// exact top-8 for one row from per-lane top-2 keys; returns row max.
__device__ __forceinline__ float topk_merge64(unsigned long long c1,
                                              unsigned long long c2,
                                              const float* __restrict__ rowS,
                                              int lane, int* __restrict__ gout) {
    unsigned long long best = c1;
    unsigned long long thresh = ~0ull;
    int cc = 0, myidx = 0;
    float rowmax = 0.f;
#pragma unroll 1
    for (int pick = 0; pick < TOPK; pick++) {
        unsigned long long w = best;
#pragma unroll
        for (int off = 16; off; off >>= 1) {
            unsigned long long o = __shfl_xor_sync(0xffffffffu, w, off);
            if (o > w) w = o;
        }
        if (pick == 0) rowmax = unpackval(w);
        if (lane == pick) myidx = unpackidx(w);
        if (best == w) {             // this lane's candidate was consumed
            cc++; thresh = w;
            if (cc == 1) best = c2;
            else {                   // rescan own strided values below threshold
                best = 0ull;
#pragma unroll 1
                for (int i = 0; i < 32; i++) {
                    int s = i * 32 + lane;
                    unsigned long long k = packkey(rowS[s], s);
                    if (k < thresh && k > best) best = k;
                }
            }
        }
    }
    if (lane < TOPK) gout[lane] = myidx;
    return rowmax;
}

// ---------------- coarse level ----------------
#define SMEM_FLOATS (LC*KVPAD + 32*LC + 32*DD)

__global__ void __launch_bounds__(512, 1) coarse_kernel() {
    extern __shared__ float sm[];
    float* sKV = sm;                  // 1024 x 20
    float* sS  = sm + LC * KVPAD;     // 32 x 1024 raw scores (later: reduce staging)
    float* sQ  = sS + 32 * LC;        // 32 x 16
    int tid = threadIdx.x;
    int w = tid >> 5, lane = tid & 31;
    int bh = blockIdx.y;
    int lbase = blockIdx.x * 32;
    const float* Qg = g_qc + ((size_t)bh * LC + lbase) * DD;
    const float* Kg = g_kc + (size_t)bh * LC * DD;
    const float* Vg = g_vc + (size_t)bh * LC * DD;

    sQ[tid] = Qg[tid];
    {
        const float4* K4 = reinterpret_cast<const float4*>(Kg);
#pragma unroll
        for (int i = tid; i < LC * DD / 4; i += 512) {
            int s = i >> 2, j = i & 3;
            *reinterpret_cast<float4*>(&sKV[s * KVPAD + j * 4]) = K4[i];
        }
    }
    __syncthreads();

    int r0 = 2 * w, r1 = 2 * w + 1;
    float4 qa[4], qb[4];
#pragma unroll
    for (int j = 0; j < 4; j++) {
        qa[j] = *reinterpret_cast<const float4*>(&sQ[r0 * DD + 4 * j]);
        qb[j] = *reinterpret_cast<const float4*>(&sQ[r1 * DD + 4 * j]);
    }

    // ---- raw scores + per-lane top-2 (packed u64 keys, exact fp32) ----
    unsigned long long a1 = 0ull, a2 = 0ull, b1 = 0ull, b2 = 0ull;
#pragma unroll 4
    for (int i = 0; i < 32; i++) {
        int s = i * 32 + lane;
        const float* kp = &sKV[s * KVPAD];
        float4 k0 = *(const float4*)(kp);
        float4 k1 = *(const float4*)(kp + 4);
        float4 k2 = *(const float4*)(kp + 8);
        float4 k3 = *(const float4*)(kp + 12);
        float s0 = dot16(qa[0], qa[1], qa[2], qa[3], k0, k1, k2, k3);
        float s1 = dot16(qb[0], qb[1], qb[2], qb[3], k0, k1, k2, k3);
        sS[r0 * LC + s] = s0;
        sS[r1 * LC + s] = s1;
        unsigned long long ka = packkey(s0, s), kb = packkey(s1, s);
        if (ka > a1) { a2 = a1; a1 = ka; } else if (ka > a2) a2 = ka;
        if (kb > b1) { b2 = b1; b1 = kb; } else if (kb > b2) b2 = kb;
    }
    __syncthreads();   // all warps done reading K

    // start V fill now; LDG latency overlaps with top-k merges below
    {
        const float4* V4 = reinterpret_cast<const float4*>(Vg);
#pragma unroll
        for (int i = tid; i < LC * DD / 4; i += 512) {
            int s = i >> 2, j = i & 3;
            *reinterpret_cast<float4*>(&sKV[s * KVPAD + j * 4]) = V4[i];
        }
    }

    float max0 = topk_merge64(a1, a2, sS + r0 * LC, lane,
                              g_topk + ((size_t)bh * LC + lbase + r0) * TOPK);
    float max1 = topk_merge64(b1, b2, sS + r1 * LC, lane,
                              g_topk + ((size_t)bh * LC + lbase + r1) * TOPK);
    __syncthreads();   // V visible to all

    // ---- fused exp + row-sum + A·V ----
    float sum0 = 0.f, sum1 = 0.f;
    float4 ac0[4], ac1[4];
#pragma unroll
    for (int j = 0; j < 4; j++) {
        ac0[j] = make_float4(0.f, 0.f, 0.f, 0.f);
        ac1[j] = make_float4(0.f, 0.f, 0.f, 0.f);
    }
#pragma unroll 4
    for (int i = 0; i < 32; i++) {
        int s = i * 32 + lane;
        float e0 = __expf(sS[r0 * LC + s] - max0);
        float e1 = __expf(sS[r1 * LC + s] - max1);
        sum0 += e0; sum1 += e1;
        const float* vp = &sKV[s * KVPAD];
        float4 v0 = *(const float4*)(vp);
        float4 v1 = *(const float4*)(vp + 4);
        float4 v2 = *(const float4*)(vp + 8);
        float4 v3 = *(const float4*)(vp + 12);
        ac0[0].x += e0*v0.x; ac0[0].y += e0*v0.y; ac0[0].z += e0*v0.z; ac0[0].w += e0*v0.w;
        ac0[1].x += e0*v1.x; ac0[1].y += e0*v1.y; ac0[1].z += e0*v1.z; ac0[1].w += e0*v1.w;
        ac0[2].x += e0*v2.x; ac0[2].y += e0*v2.y; ac0[2].z += e0*v2.z; ac0[2].w += e0*v2.w;
        ac0[3].x += e0*v3.x; ac0[3].y += e0*v3.y; ac0[3].z += e0*v3.z; ac0[3].w += e0*v3.w;
        ac1[0].x += e1*v0.x; ac1[0].y += e1*v0.y; ac1[0].z += e1*v0.z; ac1[0].w += e1*v0.w;
        ac1[1].x += e1*v1.x; ac1[1].y += e1*v1.y; ac1[1].z += e1*v1.z; ac1[1].w += e1*v1.w;
        ac1[2].x += e1*v2.x; ac1[2].y += e1*v2.y; ac1[2].z += e1*v2.z; ac1[2].w += e1*v2.w;
        ac1[3].x += e1*v3.x; ac1[3].y += e1*v3.y; ac1[3].z += e1*v3.z; ac1[3].w += e1*v3.w;
    }
    // row sums via butterfly (2 values only)
#pragma unroll
    for (int off = 16; off; off >>= 1) {
        sum0 += __shfl_xor_sync(0xffffffffu, sum0, off);
        sum1 += __shfl_xor_sync(0xffffffffu, sum1, off);
    }
    float rs0 = 1.f / sum0, rs1 = 1.f / sum1;

    // ---- A·V reduction via smem transpose (reuse this warp's score rows) ----
    __syncwarp();
    float* st0 = sS + r0 * LC;   // 16 x 33 staging, warp-private
    float* st1 = sS + r1 * LC;
    {
        const float* a0 = reinterpret_cast<const float*>(ac0);
        const float* a1f = reinterpret_cast<const float*>(ac1);
#pragma unroll
        for (int d = 0; d < 16; d++) {
            st0[d * 33 + lane] = a0[d];
            st1[d * 33 + lane] = a1f[d];
        }
    }
    __syncwarp();
    int dd = lane & 15, half = lane >> 4;
    float r0acc = 0.f, r1acc = 0.f;
#pragma unroll
    for (int j = 0; j < 16; j++) {
        r0acc += st0[dd * 33 + half * 16 + j];
        r1acc += st1[dd * 33 + half * 16 + j];
    }
    r0acc += __shfl_xor_sync(0xffffffffu, r0acc, 16);
    r1acc += __shfl_xor_sync(0xffffffffu, r1acc, 16);
    if (lane < 16) {
        g_msg0[((size_t)bh * LC + lbase + r0) * DD + dd] = r0acc * rs0;
        g_msg0[((size_t)bh * LC + lbase + r1) * DD + dd] = r1acc * rs1;
    }
}

// ---------------- fine level + combine ----------------
__global__ void __launch_bounds__(256) fine_kernel(const float* __restrict__ wptr,
                                                   float* __restrict__ out) {
    __shared__ float sQ[8][4][16];
    __shared__ float sP[8][32][4];
    __shared__ float sV[8][32][KVPAD];
    int tid = threadIdx.x, w = tid >> 5, lane = tid & 31;
    int gw = blockIdx.x * 8 + w;
    int bh = gw >> 10;
    int l  = gw & 1023;
    int b = bh >> 3, h = bh & 7;
    int lh = l >> 5, lw = l & 31;

    float w0 = wptr[0], w1 = wptr[1];
    float mw = fmaxf(w0, w1);
    float ew0 = __expf(w0 - mw), ew1 = __expf(w1 - mw);
    float rw = 1.f / (ew0 + ew1);
    float wa = ew0 * rw, wb = ew1 * rw;

    int cr = lane >> 2, off2 = lane & 3, ox = off2 >> 1, oy = off2 & 1;
    int cidx = g_topk[((size_t)bh * LC + l) * TOPK + cr];
    int py = cidx >> 5, px = cidx & (WCC - 1);
    int pos = (2 * py + ox) * WFF + 2 * px + oy;

    const float4* kp = (const float4*)(g_kf + ((size_t)bh * LF + pos) * DD);
    float4 k0 = kp[0], k1 = kp[1], k2 = kp[2], k3 = kp[3];
    const float4* vp = (const float4*)(g_vf + ((size_t)bh * LF + pos) * DD);
    float4 v0 = vp[0], v1 = vp[1], v2 = vp[2], v3 = vp[3];

    if (lane < 16) {
        int qq = lane >> 2, j = lane & 3;
        int qpos = (2 * lh + (qq >> 1)) * WFF + 2 * lw + (qq & 1);
        float4 qv = ((const float4*)(g_qf + ((size_t)bh * LF + qpos) * DD))[j];
        *reinterpret_cast<float4*>(&sQ[w][qq][4 * j]) = qv;
    }
    __syncwarp();

    float p[4];
#pragma unroll
    for (int qq = 0; qq < 4; qq++) {
        const float4* q4 = (const float4*)sQ[w][qq];
        float sc = dot16(q4[0], q4[1], q4[2], q4[3], k0, k1, k2, k3);
        float m = sc;
#pragma unroll
        for (int o = 16; o; o >>= 1) m = fmaxf(m, __shfl_xor_sync(0xffffffffu, m, o));
        float e = __expf(sc - m);
        float s = e;
#pragma unroll
        for (int o = 16; o; o >>= 1) s += __shfl_xor_sync(0xffffffffu, s, o);
        p[qq] = e / s;
    }
    *reinterpret_cast<float4*>(&sP[w][lane][0]) = make_float4(p[0], p[1], p[2], p[3]);
    float* vr = &sV[w][lane][0];
    *(float4*)(vr) = v0; *(float4*)(vr + 4) = v1;
    *(float4*)(vr + 8) = v2; *(float4*)(vr + 12) = v3;
    __syncwarp();

    int qq = lane >> 3, dp = lane & 7, d0 = dp * 2;
    float accx = 0.f, accy = 0.f;
#pragma unroll
    for (int c = 0; c < 32; c++) {
        float pc = sP[w][c][qq];
        float2 vv = *reinterpret_cast<const float2*>(&sV[w][c][d0]);
        accx += pc * vv.x;
        accy += pc * vv.y;
    }
    const float* m0p = g_msg0 + ((size_t)bh * LC + l) * DD + d0;
    float o0 = wa * m0p[0] + wb * accx;
    float o1 = wa * m0p[1] + wb * accy;
    int opos = (2 * lh + (qq >> 1)) * WFF + 2 * lw + (qq & 1);
    float* op = out + (((size_t)b * LF + opos) * NH + h) * DD + d0;
    *reinterpret_cast<float2*>(op) = make_float2(o0, o1);
}

// ---------------- launcher ----------------
extern "C" void kernel_launch(void* const* d_in, const int* in_sizes, int n_in,
                              void* d_out, int out_size) {
    (void)in_sizes; (void)n_in; (void)out_size;
    const float* qf = (const float*)d_in[0];
    const float* qc = (const float*)d_in[1];
    const float* kf = (const float*)d_in[2];
    const float* kc = (const float*)d_in[3];
    const float* vf = (const float*)d_in[4];
    const float* vc = (const float*)d_in[5];
    const float* wt = (const float*)d_in[6];
    float* out = (float*)d_out;

    void *p_qc, *p_kc, *p_vc, *p_qf, *p_kf, *p_vf;
    cudaGetSymbolAddress(&p_qc, g_qc);
    cudaGetSymbolAddress(&p_kc, g_kc);
    cudaGetSymbolAddress(&p_vc, g_vc);
    cudaGetSymbolAddress(&p_qf, g_qf);
    cudaGetSymbolAddress(&p_kf, g_kf);
    cudaGetSymbolAddress(&p_vf, g_vf);

    const float temp = 0.25f;  // 1/sqrt(16), folded into Q
    transpose3_kernel<<<dim3(LC / 256, 32, 3), 256>>>(
        qc, kc, vc, (float*)p_qc, (float*)p_kc, (float*)p_vc, LC, temp);
    transpose3_kernel<<<dim3(LF / 256, 32, 3), 256>>>(
        qf, kf, vf, (float*)p_qf, (float*)p_kf, (float*)p_vf, LF, temp);

    size_t smem = SMEM_FLOATS * sizeof(float);
    cudaFuncSetAttribute(coarse_kernel, cudaFuncAttributeMaxDynamicSharedMemorySize,
                         (int)smem);
    coarse_kernel<<<dim3(32, 32), 512, smem>>>();

    fine_kernel<<<4096, 256>>>(wt, out);
}